// round 2
// baseline (speedup 1.0000x reference)
#include <cuda_runtime.h>

#define SEQ 1024
#define NB  48
#define NROWS (NB * SEQ)           // 49152 rows, 9 channels
#define NBLK_A 144                  // 3 attns * 48 batches
#define TPB_A 512

typedef unsigned long long ull;

// scratch (allocation-free rule: __device__ globals)
__device__ float g_att[9 * NROWS];      // SoA: [channel][row]
__device__ float g_part[NBLK_A * 6];    // per-block partial sum/sumsq (3 ch each)
__device__ float g_ss[18];              // BN scale[9], shift[9]

// ---------------- packed f32x2 helpers (Blackwell) ----------------
__device__ __forceinline__ ull pack2(float lo, float hi) {
    ull r; asm("mov.b64 %0, {%1, %2};" : "=l"(r) : "f"(lo), "f"(hi)); return r;
}
__device__ __forceinline__ void unpack2(ull v, float& lo, float& hi) {
    asm("mov.b64 {%0, %1}, %2;" : "=f"(lo), "=f"(hi) : "l"(v));
}
__device__ __forceinline__ ull fma2(ull a, ull b, ull c) {
    ull d; asm("fma.rn.f32x2 %0, %1, %2, %3;" : "=l"(d) : "l"(a), "l"(b), "l"(c)); return d;
}
__device__ __forceinline__ ull mul2(ull a, ull b) {
    ull d; asm("mul.rn.f32x2 %0, %1, %2;" : "=l"(d) : "l"(a), "l"(b)); return d;
}
__device__ __forceinline__ ull add2(ull a, ull b) {
    ull d; asm("add.rn.f32x2 %0, %1, %2;" : "=l"(d) : "l"(a), "l"(b)); return d;
}
__device__ __forceinline__ ull ex2_2(ull d) {
    ull e;
    asm("{\n\t"
        ".reg .f32 dl, dh, el, eh;\n\t"
        "mov.b64 {dl, dh}, %1;\n\t"
        "ex2.approx.f32 el, dl;\n\t"
        "ex2.approx.f32 eh, dh;\n\t"
        "mov.b64 %0, {el, eh};\n\t"
        "}" : "=l"(e) : "l"(d));
    return e;
}

// ---------------------------------------------------------------------------
// Kernel A: fused projection + cross attention (packed f32x2) + BN partials
// block = (attn_idx, batch); K,V component-major in smem; thread owns 2 rows.
// ---------------------------------------------------------------------------
__global__ __launch_bounds__(TPB_A) void attn_kernel(
    const float* __restrict__ x,
    const float* __restrict__ WQ, const float* __restrict__ bQ,
    const float* __restrict__ WK, const float* __restrict__ bK,
    const float* __restrict__ WV, const float* __restrict__ bV)
{
    __shared__ __align__(16) float Kx[SEQ], Ky[SEQ], Kz[SEQ];
    __shared__ __align__(16) float Vx[SEQ], Vy[SEQ], Vz[SEQ];
    __shared__ float sred[16 * 6];

    const int blk  = blockIdx.x;
    const int attn = blk / NB;
    const int b    = blk - attn * NB;

    // a1=attn(Q2,K0,V1), a2=attn(Q0,K1,V2), a3=attn(Q1,K2,V0)
    const int qmap[3] = {2, 0, 1};
    const int vmap[3] = {1, 2, 0};
    const int qb = qmap[attn], kb = attn, vb = vmap[attn];

    const int tid = threadIdx.x;

    // ---- phase 1: K,V tiles (3x3 projection on the fly) ----
    {
        const float* wk = WK + kb * 9;  const float* bk = bK + kb * 3;
        const float* wv = WV + vb * 9;  const float* bv = bV + vb * 3;
        #pragma unroll
        for (int it = 0; it < SEQ / TPB_A; ++it) {
            int t = tid + it * TPB_A;
            const float* xk = x + ((size_t)(kb * NB + b) * SEQ + t) * 3;
            float x0 = xk[0], x1 = xk[1], x2 = xk[2];
            Kx[t] = fmaf(wk[0], x0, fmaf(wk[1], x1, fmaf(wk[2], x2, bk[0])));
            Ky[t] = fmaf(wk[3], x0, fmaf(wk[4], x1, fmaf(wk[5], x2, bk[1])));
            Kz[t] = fmaf(wk[6], x0, fmaf(wk[7], x1, fmaf(wk[8], x2, bk[2])));

            const float* xv = x + ((size_t)(vb * NB + b) * SEQ + t) * 3;
            float y0 = xv[0], y1 = xv[1], y2 = xv[2];
            Vx[t] = fmaf(wv[0], y0, fmaf(wv[1], y1, fmaf(wv[2], y2, bv[0])));
            Vy[t] = fmaf(wv[3], y0, fmaf(wv[4], y1, fmaf(wv[5], y2, bv[1])));
            Vz[t] = fmaf(wv[6], y0, fmaf(wv[7], y1, fmaf(wv[8], y2, bv[2])));
        }
    }
    __syncthreads();

    // ---- per-thread Q for rows s0=tid, s1=tid+512; fold log2e/sqrt(3) ----
    const float qscale = 1.4426950408889634f / 1.7320508075688772f;
    ull q0x, q0y, q0z, q1x, q1y, q1z;
    {
        const float* wq = WQ + qb * 9;  const float* bq = bQ + qb * 3;
        const float* xq = x + ((size_t)(qb * NB + b) * SEQ + tid) * 3;
        float x0 = xq[0], x1 = xq[1], x2 = xq[2];
        float a = fmaf(wq[0], x0, fmaf(wq[1], x1, fmaf(wq[2], x2, bq[0]))) * qscale;
        float c = fmaf(wq[3], x0, fmaf(wq[4], x1, fmaf(wq[5], x2, bq[1]))) * qscale;
        float d = fmaf(wq[6], x0, fmaf(wq[7], x1, fmaf(wq[8], x2, bq[2]))) * qscale;
        q0x = pack2(a, a); q0y = pack2(c, c); q0z = pack2(d, d);
        xq = x + ((size_t)(qb * NB + b) * SEQ + tid + TPB_A) * 3;
        x0 = xq[0]; x1 = xq[1]; x2 = xq[2];
        a = fmaf(wq[0], x0, fmaf(wq[1], x1, fmaf(wq[2], x2, bq[0]))) * qscale;
        c = fmaf(wq[3], x0, fmaf(wq[4], x1, fmaf(wq[5], x2, bq[1]))) * qscale;
        d = fmaf(wq[6], x0, fmaf(wq[7], x1, fmaf(wq[8], x2, bq[2]))) * qscale;
        q1x = pack2(a, a); q1y = pack2(c, c); q1z = pack2(d, d);
    }

    const ull* pKx = (const ull*)Kx; const ull* pKy = (const ull*)Ky;
    const ull* pKz = (const ull*)Kz; const ull* pVx = (const ull*)Vx;
    const ull* pVy = (const ull*)Vy; const ull* pVz = (const ull*)Vz;

    ull ax0 = 0, ay0 = 0, az0 = 0, aw0 = 0;
    ull ax1 = 0, ay1 = 0, az1 = 0, aw1 = 0;

    #pragma unroll 4
    for (int t2 = 0; t2 < SEQ / 2; ++t2) {
        ull kx = pKx[t2], ky = pKy[t2], kz = pKz[t2];
        ull vx = pVx[t2], vy = pVy[t2], vz = pVz[t2];

        ull d0 = fma2(q0x, kx, fma2(q0y, ky, mul2(q0z, kz)));
        ull e0 = ex2_2(d0);
        ax0 = fma2(e0, vx, ax0);
        ay0 = fma2(e0, vy, ay0);
        az0 = fma2(e0, vz, az0);
        aw0 = add2(aw0, e0);

        ull d1 = fma2(q1x, kx, fma2(q1y, ky, mul2(q1z, kz)));
        ull e1 = ex2_2(d1);
        ax1 = fma2(e1, vx, ax1);
        ay1 = fma2(e1, vy, ay1);
        az1 = fma2(e1, vz, az1);
        aw1 = add2(aw1, e1);
    }

    // horizontal reduce packed halves
    float l, h;
    unpack2(aw0, l, h); const float inv0 = 1.0f / (l + h);
    unpack2(aw1, l, h); const float inv1 = 1.0f / (l + h);
    unpack2(ax0, l, h); const float o00 = (l + h) * inv0;
    unpack2(ay0, l, h); const float o01 = (l + h) * inv0;
    unpack2(az0, l, h); const float o02 = (l + h) * inv0;
    unpack2(ax1, l, h); const float o10 = (l + h) * inv1;
    unpack2(ay1, l, h); const float o11 = (l + h) * inv1;
    unpack2(az1, l, h); const float o12 = (l + h) * inv1;

    // SoA coalesced store: channel = attn*3 + i
    {
        const size_t r0 = (size_t)b * SEQ + tid;
        const size_t r1 = r0 + TPB_A;
        float* c0 = g_att + (size_t)(attn * 3 + 0) * NROWS;
        float* c1 = g_att + (size_t)(attn * 3 + 1) * NROWS;
        float* c2 = g_att + (size_t)(attn * 3 + 2) * NROWS;
        c0[r0] = o00; c1[r0] = o01; c2[r0] = o02;
        c0[r1] = o10; c1[r1] = o11; c2[r1] = o12;
    }

    // ---- BN partial stats (deterministic) ----
    float sm[3], sq[3];
    sm[0] = o00 + o10; sm[1] = o01 + o11; sm[2] = o02 + o12;
    sq[0] = o00 * o00 + o10 * o10;
    sq[1] = o01 * o01 + o11 * o11;
    sq[2] = o02 * o02 + o12 * o12;

    #pragma unroll
    for (int off = 16; off > 0; off >>= 1) {
        #pragma unroll
        for (int i = 0; i < 3; ++i) {
            sm[i] += __shfl_down_sync(0xFFFFFFFFu, sm[i], off);
            sq[i] += __shfl_down_sync(0xFFFFFFFFu, sq[i], off);
        }
    }
    const int warp = tid >> 5, lane = tid & 31;
    if (lane == 0) {
        #pragma unroll
        for (int i = 0; i < 3; ++i) {
            sred[warp * 6 + i]     = sm[i];
            sred[warp * 6 + 3 + i] = sq[i];
        }
    }
    __syncthreads();
    if (tid == 0) {
        float acc[6] = {0.f, 0.f, 0.f, 0.f, 0.f, 0.f};
        #pragma unroll
        for (int w = 0; w < 16; ++w)
            #pragma unroll
            for (int i = 0; i < 6; ++i)
                acc[i] += sred[w * 6 + i];
        #pragma unroll
        for (int i = 0; i < 6; ++i)
            g_part[blk * 6 + i] = acc[i];
    }
}

// ---------------------------------------------------------------------------
// Kernel C: finalize BN stats once (1 block, warp w = channel w)
// ---------------------------------------------------------------------------
__global__ __launch_bounds__(288) void stats_kernel(
    const float* __restrict__ gamma, const float* __restrict__ beta)
{
    const int w = threadIdx.x >> 5, lane = threadIdx.x & 31;
    if (w >= 9) return;
    const int at = w / 3, d = w - at * 3;
    float sm = 0.f, sq = 0.f;
    for (int i = lane; i < NB; i += 32) {
        const float* p = g_part + (size_t)(at * NB + i) * 6;
        sm += p[d];
        sq += p[3 + d];
    }
    #pragma unroll
    for (int off = 16; off > 0; off >>= 1) {
        sm += __shfl_down_sync(0xFFFFFFFFu, sm, off);
        sq += __shfl_down_sync(0xFFFFFFFFu, sq, off);
    }
    if (lane == 0) {
        const float mean = sm * (1.0f / NROWS);
        const float var  = sq * (1.0f / NROWS) - mean * mean;
        const float inv  = rsqrtf(var + 1e-5f);
        const float sc   = gamma[w] * inv;
        g_ss[w]     = sc;
        g_ss[9 + w] = beta[w] - mean * sc;
    }
}

// ---------------------------------------------------------------------------
// Kernel B: BN + FC (reads precomputed scale/shift; SoA coalesced reads)
// ---------------------------------------------------------------------------
__global__ __launch_bounds__(256) void bnfc_kernel(
    const float* __restrict__ fcw, const float* __restrict__ fcb,
    float* __restrict__ out)
{
    __shared__ float ss[18];
    const int tid = threadIdx.x;
    if (tid < 18) ss[tid] = g_ss[tid];
    __syncthreads();

    const int row = blockIdx.x * 256 + tid;   // grid covers NROWS exactly
    float n[9];
    #pragma unroll
    for (int c = 0; c < 9; ++c)
        n[c] = fmaf(g_att[(size_t)c * NROWS + row], ss[c], ss[9 + c]);
    #pragma unroll
    for (int j = 0; j < 3; ++j) {
        float y = fcb[j];
        #pragma unroll
        for (int c = 0; c < 9; ++c)
            y = fmaf(n[c], fcw[j * 9 + c], y);
        out[row * 3 + j] = y;
    }
}

// ---------------------------------------------------------------------------
extern "C" void kernel_launch(void* const* d_in, const int* in_sizes, int n_in,
                              void* d_out, int out_size)
{
    const float* x     = (const float*)d_in[0];
    const float* WQ    = (const float*)d_in[1];
    const float* bQ    = (const float*)d_in[2];
    const float* WK    = (const float*)d_in[3];
    const float* bK    = (const float*)d_in[4];
    const float* WV    = (const float*)d_in[5];
    const float* bV    = (const float*)d_in[6];
    const float* gamma = (const float*)d_in[7];
    const float* beta  = (const float*)d_in[8];
    const float* fcw   = (const float*)d_in[9];
    const float* fcb   = (const float*)d_in[10];

    attn_kernel<<<NBLK_A, TPB_A>>>(x, WQ, bQ, WK, bK, WV, bV);
    stats_kernel<<<1, 288>>>(gamma, beta);
    bnfc_kernel<<<NROWS / 256, 256>>>(fcw, fcb, (float*)d_out);
}